// round 14
// baseline (speedup 1.0000x reference)
#include <cuda_runtime.h>
#include <cuda_fp16.h>
#include <cstdint>

#define BB 32
#define LL 2048
#define CC 512
#define QQ 512
#define HH 1024

// ---------------- scratch (no allocations allowed) ----------------
__device__ float g_resq[BB * HH];          // res_q
__device__ float g_logit[BB * LL];         // compacted logits
__device__ float g_wcmp[BB * LL];          // compacted weights
__device__ float g_part[BB * 32 * CC];     // 2 MB partials
__device__ __half g_wc_h[HH * CC];         // Wc in fp16, [h][k]
__device__ int   g_idx[BB * LL];           // compacted row indices
__device__ int   g_cnt[BB];                // unmasked count per batch

// ---------------- helpers ----------------
__device__ __forceinline__ uint32_t smem_u32(const void* p) {
    uint32_t a;
    asm("{ .reg .u64 t; cvta.to.shared.u64 t, %1; cvt.u32.u64 %0, t; }"
        : "=r"(a) : "l"(p));
    return a;
}

__device__ __forceinline__ void ldsm4(uint32_t& r0, uint32_t& r1,
                                      uint32_t& r2, uint32_t& r3, uint32_t addr) {
    asm volatile("ldmatrix.sync.aligned.m8n8.x4.shared.b16 {%0,%1,%2,%3}, [%4];"
                 : "=r"(r0), "=r"(r1), "=r"(r2), "=r"(r3) : "r"(addr));
}

// fp16-accumulate MMA (2x rate of f32-acc on the legacy HMMA pipe)
__device__ __forceinline__ void mma16816_f16(uint32_t& c0, uint32_t& c1,
                                             uint32_t a0, uint32_t a1,
                                             uint32_t a2, uint32_t a3,
                                             uint32_t b0, uint32_t b1) {
    asm volatile(
        "mma.sync.aligned.m16n8k16.row.col.f16.f16.f16.f16 "
        "{%0,%1}, {%2,%3,%4,%5}, {%6,%7}, {%0,%1};"
        : "+r"(c0), "+r"(c1)
        : "r"(a0), "r"(a1), "r"(a2), "r"(a3), "r"(b0), "r"(b1));
}

__device__ __forceinline__ void cp_async16(uint32_t dst, const void* src) {
    asm volatile("cp.async.cg.shared.global [%0], [%1], 16;" :: "r"(dst), "l"(src));
}
#define CP_COMMIT() asm volatile("cp.async.commit_group;" ::: "memory")
#define CP_WAIT0()  asm volatile("cp.async.wait_group 0;" ::: "memory")

// MUFU-pipe tanh
__device__ __forceinline__ float tanh_mufu(float x) {
    float t = __expf(2.0f * x);
    return 1.0f - __fdividef(2.0f, t + 1.0f);
}

// ---------------- kernel P: merged prep (wcprep | resq | compact) ----------
__global__ __launch_bounds__(256) void prep_kernel(
    const float* __restrict__ Wc, const float* __restrict__ query,
    const float* __restrict__ Wq, const float* __restrict__ mask) {
    const int blk = blockIdx.x;
    const int t = threadIdx.x;

    if (blk < 512) {                       // ---- Wc -> fp16 ----
        const int i = blk * 256 + t;
        float4 v = reinterpret_cast<const float4*>(Wc)[i];
        __half2 h0 = __floats2half2_rn(v.x, v.y);
        __half2 h1 = __floats2half2_rn(v.z, v.w);
        uint2 u;
        u.x = *reinterpret_cast<uint32_t*>(&h0);
        u.y = *reinterpret_cast<uint32_t*>(&h1);
        reinterpret_cast<uint2*>(g_wc_h)[i] = u;
        return;
    }

    if (blk < 640) {                       // ---- res_q: Wq read ONCE ----
        __shared__ float wq_s[8][516];
        const int rb = blk - 512;
        const int h_base = rb * 8;
        for (int i = t; i < 1024; i += 256) {
            const int row = i >> 7, c4 = i & 127;
            const float4 v = *(const float4*)(Wq + (size_t)(h_base + row) * QQ + c4 * 4);
            *(float4*)&wq_s[row][c4 * 4] = v;
        }
        __syncthreads();
        const int h_local = t & 7, bq = t >> 3;
        const float* qrow = query + (size_t)bq * QQ;
        const float* wrow = wq_s[h_local];
        float acc = 0.f;
#pragma unroll 8
        for (int c4 = 0; c4 < 128; c4++) {
            const float4 qv = *(const float4*)(qrow + c4 * 4);
            const float4 wv = *(const float4*)(wrow + c4 * 4);
            acc += wv.x * qv.x + wv.y * qv.y + wv.z * qv.z + wv.w * qv.w;
        }
        g_resq[bq * HH + h_base + h_local] = acc;
        return;
    }

    // ---- compaction (ballot-based, stable) ----
    {
        __shared__ int warpsum[8];
        __shared__ int sbase;
        const int b = blk - 640;
        const int lane = t & 31, warp = t >> 5;
        if (t == 0) sbase = 0;
        __syncthreads();
        for (int ch = 0; ch < 8; ch++) {
            const int l = ch * 256 + t;
            const int flag = (mask[b * LL + l] != 0.0f) ? 1 : 0;
            const uint32_t bal = __ballot_sync(0xffffffffu, flag);
            const int wpre = __popc(bal & ((1u << lane) - 1u));
            if (lane == 0) warpsum[warp] = __popc(bal);
            __syncthreads();
            int base = 0, ctot = 0;
#pragma unroll
            for (int w = 0; w < 8; w++) {
                base += (w < warp) ? warpsum[w] : 0;
                ctot += warpsum[w];
            }
            if (flag) g_idx[b * LL + sbase + base + wpre] = l;
            __syncthreads();
            if (t == 0) sbase += ctot;
            __syncthreads();
        }
        if (t == 0) g_cnt[b] = sbase;
    }
}

// ---------------- kernel 2: mma.sync fused GEMM + tanh + Wo-reduce ----------
// Compacted rows. CTA = 64 rows, occ 2, warps 2Mx4N. 2-stage cp.async pipe.
// NEW: fp16-accumulate MMA within each K=64 chunk (rt=4), promoted to fp32
// accumulators once per chunk (error ~= existing fp16 input quantization).
#define A_SZ    65536                 // 64 x 512 fp16
#define B_SZ    16384                 // 128 x 64 fp16
#define RQ_OFF  (A_SZ + 2 * B_SZ)     // 98304
#define WO_OFF  (RQ_OFF + 4096)
#define RED_OFF (WO_OFF + 4096)
#define SM_REQ  (RED_OFF + 768 + 128)

__global__ __launch_bounds__(256, 2) void logits_mma_kernel(
    const float* __restrict__ ctx, const float* __restrict__ bc,
    const float* __restrict__ Wo, const float* __restrict__ bo) {
    const int b = blockIdx.x >> 5;
    const int m0 = (blockIdx.x & 31) * 64;
    const int cnt = g_cnt[b];
    if (m0 >= cnt) return;

    extern __shared__ char smraw[];
    __shared__ int rid_s[64];
    const uint32_t sb_raw = smem_u32(smraw);
    const uint32_t sb = (sb_raw + 127u) & ~127u;
    char* sm = smraw + (sb - sb_raw);

    const int t = threadIdx.x;
    const int lane = t & 31, warp = t >> 5;
    const int mg = warp >> 2;
    const int ng = warp & 3;

    const uint32_t sb_B = sb + A_SZ;

    // ---- strength-reduced fill_B constants ----
    const int fc = t & 7;
    const int frow0 = t >> 3;
    uint32_t fdst[4];
    const __half* fsrc[4];
#pragma unroll
    for (int i = 0; i < 4; i++) {
        const int row = frow0 + i * 32;
        fdst[i] = sb_B + (uint32_t)(row * 128 + ((fc ^ (row & 7)) << 4));
        fsrc[i] = g_wc_h + (size_t)row * CC + fc * 8;
    }

    auto fill_B = [&](uint32_t bufoff, int it) {
        const int goff = ((it >> 3) << 16) + ((it & 7) << 6);
#pragma unroll
        for (int i = 0; i < 4; i++)
            cp_async16(fdst[i] + bufoff, fsrc[i] + goff);
        CP_COMMIT();
    };

    fill_B(0, 0);                     // streams while A-fill runs below

    float* rqs_s = (float*)(sm + RQ_OFF);
    float* wos_s = (float*)(sm + WO_OFF);
    float* red_s = (float*)(sm + RED_OFF);
#pragma unroll
    for (int i = 0; i < 4; i++) {
        const int n = t + i * 256;
        rqs_s[n] = g_resq[b * HH + n] + bc[n];
        wos_s[n] = Wo[n];
    }
    if (t < 64) {
        const int rsel = min(m0 + t, cnt - 1);
        rid_s[t] = g_idx[b * LL + rsel];
    }
    __syncthreads();

    // ---- fill A: gathered ctx rows -> fp16 swizzled ----
#pragma unroll 4
    for (int i = 0; i < 16; i++) {
        const int idx = t + i * 256;
        const int row = idx >> 6, c = idx & 63;
        const float4* s = (const float4*)(ctx + ((size_t)b * LL + rid_s[row]) * CC + c * 8);
        float4 v0 = s[0], v1 = s[1];
        __half2 h0 = __floats2half2_rn(v0.x, v0.y);
        __half2 h1 = __floats2half2_rn(v0.z, v0.w);
        __half2 h2 = __floats2half2_rn(v1.x, v1.y);
        __half2 h3 = __floats2half2_rn(v1.z, v1.w);
        uint4 u;
        u.x = *reinterpret_cast<uint32_t*>(&h0);
        u.y = *reinterpret_cast<uint32_t*>(&h1);
        u.z = *reinterpret_cast<uint32_t*>(&h2);
        u.w = *reinterpret_cast<uint32_t*>(&h3);
        *(uint4*)(sm + row * 1024 + (((c ^ (row & 7))) << 4)) = u;
    }

    // ---- strength-reduced LDSM constants ----
    const uint32_t a_row_addr = sb + (mg * 32 + (lane & 15)) * 1024;
    const int a_hi = lane >> 4;
    const int asw = lane & 7;
    uint32_t aoffC[4];
#pragma unroll
    for (int ks = 0; ks < 4; ks++)
        aoffC[ks] = (uint32_t)(((ks * 2 + a_hi) ^ asw) << 4);

    const int brow = (lane & 7) + ((lane & 16) >> 1);
    const int bkbit = (lane >> 3) & 1;
    const int bsw = lane & 7;
    uint32_t boffC[4];
#pragma unroll
    for (int ks = 0; ks < 4; ks++)
        boffC[ks] = (uint32_t)(((ks * 2 + bkbit) ^ bsw) << 4);
    const uint32_t bbase0 = sb_B + (uint32_t)ng * 32 * 128 + (uint32_t)(brow << 7);
    const uint32_t bbase1 = bbase0 + B_SZ;
    const uint32_t browoff1 = 16u << 7;

    float p[4] = {0.f, 0.f, 0.f, 0.f};
    const float bo0 = bo[0];

    for (int nt = 0; nt < 8; nt++) {
        float acc[2][4][4];
#pragma unroll
        for (int mt = 0; mt < 2; mt++)
#pragma unroll
            for (int nb = 0; nb < 4; nb++)
#pragma unroll
                for (int j = 0; j < 4; j++) acc[mt][nb][j] = 0.f;

        for (int kk = 0; kk < 8; kk++) {
            const int it = nt * 8 + kk;
            CP_WAIT0();
            __syncthreads();
            if (it + 1 < 64) fill_B(((it + 1) & 1) ? B_SZ : 0u, it + 1);

            const uint32_t bb = (it & 1) ? bbase1 : bbase0;
            const uint32_t arow = a_row_addr + ((uint32_t)kk << 7);

            // fp16 chunk accumulators (K=64 per chunk)
            uint32_t hAcc[2][4][2];
#pragma unroll
            for (int mt = 0; mt < 2; mt++)
#pragma unroll
                for (int nb = 0; nb < 4; nb++) {
                    hAcc[mt][nb][0] = 0u;
                    hAcc[mt][nb][1] = 0u;
                }

#pragma unroll
            for (int ks = 0; ks < 4; ks++) {
                uint32_t a[2][4];
                ldsm4(a[0][0], a[0][1], a[0][2], a[0][3], arow + aoffC[ks]);
                ldsm4(a[1][0], a[1][1], a[1][2], a[1][3], arow + 16384 + aoffC[ks]);
                uint32_t bf[2][4];
                ldsm4(bf[0][0], bf[0][1], bf[0][2], bf[0][3], bb + boffC[ks]);
                ldsm4(bf[1][0], bf[1][1], bf[1][2], bf[1][3], bb + browoff1 + boffC[ks]);
#pragma unroll
                for (int mt = 0; mt < 2; mt++)
#pragma unroll
                    for (int pq = 0; pq < 2; pq++) {
                        mma16816_f16(hAcc[mt][2 * pq][0],     hAcc[mt][2 * pq][1],
                                     a[mt][0], a[mt][1], a[mt][2], a[mt][3],
                                     bf[pq][0], bf[pq][1]);
                        mma16816_f16(hAcc[mt][2 * pq + 1][0], hAcc[mt][2 * pq + 1][1],
                                     a[mt][0], a[mt][1], a[mt][2], a[mt][3],
                                     bf[pq][2], bf[pq][3]);
                    }
            }

            // promote chunk sums to fp32
#pragma unroll
            for (int mt = 0; mt < 2; mt++)
#pragma unroll
                for (int nb = 0; nb < 4; nb++) {
                    const float2 f0 = __half22float2(
                        *reinterpret_cast<__half2*>(&hAcc[mt][nb][0]));
                    const float2 f1 = __half22float2(
                        *reinterpret_cast<__half2*>(&hAcc[mt][nb][1]));
                    acc[mt][nb][0] += f0.x;
                    acc[mt][nb][1] += f0.y;
                    acc[mt][nb][2] += f1.x;
                    acc[mt][nb][3] += f1.y;
                }
        }

        // ---- fused epilogue for n-tile nt ----
#pragma unroll
        for (int mt = 0; mt < 2; mt++)
#pragma unroll
            for (int nb = 0; nb < 4; nb++) {
                const int ngl = nt * 128 + ng * 32 + nb * 8 + ((lane & 3) << 1);
                const float rq0 = rqs_s[ngl],     w0 = wos_s[ngl];
                const float rq1 = rqs_s[ngl + 1], w1 = wos_s[ngl + 1];
                p[2 * mt]     += w0 * tanh_mufu(acc[mt][nb][0] + rq0);
                p[2 * mt]     += w1 * tanh_mufu(acc[mt][nb][1] + rq1);
                p[2 * mt + 1] += w0 * tanh_mufu(acc[mt][nb][2] + rq0);
                p[2 * mt + 1] += w1 * tanh_mufu(acc[mt][nb][3] + rq1);
            }
    }

#pragma unroll
    for (int j = 0; j < 4; j++) {
        p[j] += __shfl_xor_sync(0xffffffffu, p[j], 1);
        p[j] += __shfl_xor_sync(0xffffffffu, p[j], 2);
    }
    if (ng > 0 && (lane & 3) == 0) {
        float* dst = red_s + (ng - 1) * 64 + mg * 32 + (lane >> 2);
        dst[0]  = p[0];
        dst[8]  = p[1];
        dst[16] = p[2];
        dst[24] = p[3];
    }
    __syncthreads();
    if (ng == 0 && (lane & 3) == 0) {
        const int r = mg * 32 + (lane >> 2);
#pragma unroll
        for (int j = 0; j < 4; j++) {
            const int row = r + 8 * j;
            if (m0 + row < cnt)
                g_logit[b * LL + m0 + row] = p[j] + red_s[row] + red_s[64 + row]
                                           + red_s[128 + row] + bo0;
        }
    }
}

// ---------------- kernel 3: masked exp + normalize (compacted) -------------
__global__ void softmax_kernel(const float* __restrict__ mask,
                               float* __restrict__ w_out, int write_w) {
    __shared__ float sred[256];
    const int b = blockIdx.x, t = threadIdx.x;
    const int cnt = g_cnt[b];
    if (write_w) {
        for (int i = t; i < LL; i += 256) w_out[b * LL + i] = 0.f;
    }
    float e[8];
    int ids[8];
    float s = 0.f;
#pragma unroll
    for (int i = 0; i < 8; i++) {
        const int j = t + i * 256;
        float ev = 0.f;
        int id = -1;
        if (j < cnt) {
            id = g_idx[b * LL + j];
            ev = mask[b * LL + id] * expf(g_logit[b * LL + j]);
        }
        e[i] = ev;
        ids[i] = id;
        s += ev;
    }
    sred[t] = s;
    __syncthreads();
#pragma unroll
    for (int off = 128; off > 0; off >>= 1) {
        if (t < off) sred[t] += sred[t + off];
        __syncthreads();
    }
    const float inv = 1.f / (sred[0] + 1e-5f);
#pragma unroll
    for (int i = 0; i < 8; i++) {
        if (ids[i] >= 0) {
            const float wv = e[i] * inv;
            g_wcmp[b * LL + t + i * 256] = wv;
            if (write_w) w_out[b * LL + ids[i]] = wv;
        }
    }
}

// ---------------- kernel 4: weighted sum, float4 + explicit 8-deep pipeline -
__global__ void wsum_kernel(const float* __restrict__ ctx) {
    const int b = blockIdx.x, seg = blockIdx.y, t = threadIdx.x;
    const int cnt = g_cnt[b];
    const int tc = t & 127, half = t >> 7;
    float4* dstq = (float4*)(g_part + (size_t)(b * 32 + seg) * CC) + tc;
    if (seg * 64 >= cnt) {
        if (half == 0) *dstq = make_float4(0.f, 0.f, 0.f, 0.f);
        return;
    }
    __shared__ float ws[64];
    __shared__ int wi[64];
    __shared__ float4 xch[128];
    if (t < 64) {
        const int j = seg * 64 + t;
        if (j < cnt) { ws[t] = g_wcmp[b * LL + j]; wi[t] = g_idx[b * LL + j]; }
        else         { ws[t] = 0.f;                wi[t] = 0; }
    }
    __syncthreads();
    const float4* cb = (const float4*)(ctx + (size_t)b * LL * CC) + tc;
    float4 acc = make_float4(0.f, 0.f, 0.f, 0.f);
    float4 buf[8];
    float wv[8];
#pragma unroll
    for (int i = 0; i < 8; i++) {
        const int r = half + 2 * i;
        buf[i] = cb[(size_t)wi[r] * 128];
        wv[i] = ws[r];
    }
#pragma unroll
    for (int li = 0; li < 32; li++) {
        const float4 v = buf[li & 7];
        const float w = wv[li & 7];
        if (li + 8 < 32) {
            const int r = half + 2 * (li + 8);
            buf[li & 7] = cb[(size_t)wi[r] * 128];
            wv[li & 7] = ws[r];
        }
        acc.x = fmaf(w, v.x, acc.x);
        acc.y = fmaf(w, v.y, acc.y);
        acc.z = fmaf(w, v.z, acc.z);
        acc.w = fmaf(w, v.w, acc.w);
    }
    if (half == 1) xch[tc] = acc;
    __syncthreads();
    if (half == 0) {
        const float4 o = xch[tc];
        acc.x += o.x;
        acc.y += o.y;
        acc.z += o.z;
        acc.w += o.w;
        *dstq = acc;
    }
}

__global__ void reduce_kernel(float* __restrict__ out_vec) {
    const int idx = blockIdx.x * 256 + threadIdx.x;
    const int b = idx >> 9, c = idx & 511;
    float s = 0.f;
#pragma unroll
    for (int ls = 0; ls < 32; ls++) s += g_part[(size_t)(b * 32 + ls) * CC + c];
    out_vec[b * CC + c] = s;
}

// ---------------- launch ----------------
extern "C" void kernel_launch(void* const* d_in, const int* in_sizes, int n_in,
                              void* d_out, int out_size) {
    const float* query   = (const float*)d_in[0];
    const float* context = (const float*)d_in[1];
    const float* mask    = (const float*)d_in[2];
    const float* Wq      = (const float*)d_in[3];
    const float* Wc      = (const float*)d_in[4];
    const float* bc      = (const float*)d_in[5];
    const float* Wo      = (const float*)d_in[6];
    const float* bo      = (const float*)d_in[7];

    float* out = (float*)d_out;
    float* out_vec = nullptr;
    float* out_w = nullptr;
    if (out_size >= BB * CC + BB * LL) {
        out_vec = out;
        out_w = out + BB * CC;
    } else if (out_size == BB * LL) {
        out_w = out;
    } else {
        out_vec = out;
    }

    cudaFuncSetAttribute(logits_mma_kernel,
                         cudaFuncAttributeMaxDynamicSharedMemorySize, SM_REQ);

    prep_kernel<<<672, 256>>>(Wc, query, Wq, mask);
    logits_mma_kernel<<<(BB * LL) / 64, 256, SM_REQ>>>(context, bc, Wo, bo);
    softmax_kernel<<<BB, 256>>>(mask, out_w, out_w != nullptr ? 1 : 0);
    wsum_kernel<<<dim3(BB, 32), 256>>>(context);
    if (out_vec) reduce_kernel<<<(BB * CC) / 256, 256>>>(out_vec);
}

// round 15
// speedup vs baseline: 1.1214x; 1.1214x over previous
#include <cuda_runtime.h>
#include <cuda_fp16.h>
#include <cstdint>

#define BB 32
#define LL 2048
#define CC 512
#define QQ 512
#define HH 1024

// ---------------- scratch (no allocations allowed) ----------------
__device__ float g_resq[BB * HH];          // res_q
__device__ float g_logit[BB * LL];         // compacted logits
__device__ float g_wcmp[BB * LL];          // compacted weights
__device__ float g_part[BB * 32 * CC];     // 2 MB partials
__device__ __half g_wc_h[HH * CC];         // Wc in fp16, [h][k]
__device__ int   g_idx[BB * LL];           // compacted row indices
__device__ int   g_cnt[BB];                // unmasked count per batch
__device__ int   g_wcnt[BB];               // wsum arrival counters

// ---------------- helpers ----------------
__device__ __forceinline__ uint32_t smem_u32(const void* p) {
    uint32_t a;
    asm("{ .reg .u64 t; cvta.to.shared.u64 t, %1; cvt.u32.u64 %0, t; }"
        : "=r"(a) : "l"(p));
    return a;
}

__device__ __forceinline__ void ldsm4(uint32_t& r0, uint32_t& r1,
                                      uint32_t& r2, uint32_t& r3, uint32_t addr) {
    asm volatile("ldmatrix.sync.aligned.m8n8.x4.shared.b16 {%0,%1,%2,%3}, [%4];"
                 : "=r"(r0), "=r"(r1), "=r"(r2), "=r"(r3) : "r"(addr));
}

__device__ __forceinline__ void mma16816(float* c,
                                         uint32_t a0, uint32_t a1, uint32_t a2, uint32_t a3,
                                         uint32_t b0, uint32_t b1) {
    asm volatile(
        "mma.sync.aligned.m16n8k16.row.col.f32.f16.f16.f32 "
        "{%0,%1,%2,%3}, {%4,%5,%6,%7}, {%8,%9}, {%0,%1,%2,%3};"
        : "+f"(c[0]), "+f"(c[1]), "+f"(c[2]), "+f"(c[3])
        : "r"(a0), "r"(a1), "r"(a2), "r"(a3), "r"(b0), "r"(b1));
}

__device__ __forceinline__ void cp_async16(uint32_t dst, const void* src) {
    asm volatile("cp.async.cg.shared.global [%0], [%1], 16;" :: "r"(dst), "l"(src));
}
#define CP_COMMIT() asm volatile("cp.async.commit_group;" ::: "memory")
#define CP_WAIT0()  asm volatile("cp.async.wait_group 0;" ::: "memory")

// MUFU-pipe tanh
__device__ __forceinline__ float tanh_mufu(float x) {
    float t = __expf(2.0f * x);
    return 1.0f - __fdividef(2.0f, t + 1.0f);
}

// ---------------- kernel P: merged prep (wcprep | resq | compact) ----------
__global__ __launch_bounds__(256) void prep_kernel(
    const float* __restrict__ Wc, const float* __restrict__ query,
    const float* __restrict__ Wq, const float* __restrict__ mask) {
    const int blk = blockIdx.x;
    const int t = threadIdx.x;

    if (blk < 512) {                       // ---- Wc -> fp16 ----
        const int i = blk * 256 + t;
        float4 v = reinterpret_cast<const float4*>(Wc)[i];
        __half2 h0 = __floats2half2_rn(v.x, v.y);
        __half2 h1 = __floats2half2_rn(v.z, v.w);
        uint2 u;
        u.x = *reinterpret_cast<uint32_t*>(&h0);
        u.y = *reinterpret_cast<uint32_t*>(&h1);
        reinterpret_cast<uint2*>(g_wc_h)[i] = u;
        return;
    }

    if (blk < 640) {                       // ---- res_q: Wq read ONCE ----
        __shared__ float wq_s[8][516];
        const int rb = blk - 512;
        const int h_base = rb * 8;
        for (int i = t; i < 1024; i += 256) {
            const int row = i >> 7, c4 = i & 127;
            const float4 v = *(const float4*)(Wq + (size_t)(h_base + row) * QQ + c4 * 4);
            *(float4*)&wq_s[row][c4 * 4] = v;
        }
        __syncthreads();
        const int h_local = t & 7, bq = t >> 3;
        const float* qrow = query + (size_t)bq * QQ;
        const float* wrow = wq_s[h_local];
        float acc = 0.f;
#pragma unroll 8
        for (int c4 = 0; c4 < 128; c4++) {
            const float4 qv = *(const float4*)(qrow + c4 * 4);
            const float4 wv = *(const float4*)(wrow + c4 * 4);
            acc += wv.x * qv.x + wv.y * qv.y + wv.z * qv.z + wv.w * qv.w;
        }
        g_resq[bq * HH + h_base + h_local] = acc;
        return;
    }

    // ---- compaction (ballot-based, stable) ----
    {
        __shared__ int warpsum[8];
        __shared__ int sbase;
        const int b = blk - 640;
        const int lane = t & 31, warp = t >> 5;
        if (t == 0) sbase = 0;
        __syncthreads();
        for (int ch = 0; ch < 8; ch++) {
            const int l = ch * 256 + t;
            const int flag = (mask[b * LL + l] != 0.0f) ? 1 : 0;
            const uint32_t bal = __ballot_sync(0xffffffffu, flag);
            const int wpre = __popc(bal & ((1u << lane) - 1u));
            if (lane == 0) warpsum[warp] = __popc(bal);
            __syncthreads();
            int base = 0, ctot = 0;
#pragma unroll
            for (int w = 0; w < 8; w++) {
                base += (w < warp) ? warpsum[w] : 0;
                ctot += warpsum[w];
            }
            if (flag) g_idx[b * LL + sbase + base + wpre] = l;
            __syncthreads();
            if (t == 0) sbase += ctot;
            __syncthreads();
        }
        if (t == 0) g_cnt[b] = sbase;
    }
}

// ---------------- kernel 2: mma.sync fused GEMM + tanh + Wo-reduce ----------
// (proven 155.8us config) Compacted rows. CTA = 64 rows, occ 2, warps 2Mx4N.
// 2-stage cp.async B pipeline; first B fill hoisted above A-fill prologue.
#define A_SZ    65536                 // 64 x 512 fp16
#define B_SZ    16384                 // 128 x 64 fp16
#define RQ_OFF  (A_SZ + 2 * B_SZ)     // 98304
#define WO_OFF  (RQ_OFF + 4096)
#define RED_OFF (WO_OFF + 4096)
#define SM_REQ  (RED_OFF + 768 + 128)

__global__ __launch_bounds__(256, 2) void logits_mma_kernel(
    const float* __restrict__ ctx, const float* __restrict__ bc,
    const float* __restrict__ Wo, const float* __restrict__ bo) {
    const int b = blockIdx.x >> 5;
    const int m0 = (blockIdx.x & 31) * 64;
    const int cnt = g_cnt[b];
    if (m0 >= cnt) return;

    extern __shared__ char smraw[];
    __shared__ int rid_s[64];
    const uint32_t sb_raw = smem_u32(smraw);
    const uint32_t sb = (sb_raw + 127u) & ~127u;
    char* sm = smraw + (sb - sb_raw);

    const int t = threadIdx.x;
    const int lane = t & 31, warp = t >> 5;
    const int mg = warp >> 2;
    const int ng = warp & 3;

    const uint32_t sb_B = sb + A_SZ;

    // ---- strength-reduced fill_B constants ----
    const int fc = t & 7;
    const int frow0 = t >> 3;
    uint32_t fdst[4];
    const __half* fsrc[4];
#pragma unroll
    for (int i = 0; i < 4; i++) {
        const int row = frow0 + i * 32;
        fdst[i] = sb_B + (uint32_t)(row * 128 + ((fc ^ (row & 7)) << 4));
        fsrc[i] = g_wc_h + (size_t)row * CC + fc * 8;
    }

    auto fill_B = [&](uint32_t bufoff, int it) {
        const int goff = ((it >> 3) << 16) + ((it & 7) << 6);
#pragma unroll
        for (int i = 0; i < 4; i++)
            cp_async16(fdst[i] + bufoff, fsrc[i] + goff);
        CP_COMMIT();
    };

    fill_B(0, 0);                     // streams while A-fill runs below

    float* rqs_s = (float*)(sm + RQ_OFF);
    float* wos_s = (float*)(sm + WO_OFF);
    float* red_s = (float*)(sm + RED_OFF);
#pragma unroll
    for (int i = 0; i < 4; i++) {
        const int n = t + i * 256;
        rqs_s[n] = g_resq[b * HH + n] + bc[n];
        wos_s[n] = Wo[n];
    }
    if (t < 64) {
        const int rsel = min(m0 + t, cnt - 1);
        rid_s[t] = g_idx[b * LL + rsel];
    }
    __syncthreads();

    // ---- fill A: gathered ctx rows -> fp16 swizzled ----
#pragma unroll 4
    for (int i = 0; i < 16; i++) {
        const int idx = t + i * 256;
        const int row = idx >> 6, c = idx & 63;
        const float4* s = (const float4*)(ctx + ((size_t)b * LL + rid_s[row]) * CC + c * 8);
        float4 v0 = s[0], v1 = s[1];
        __half2 h0 = __floats2half2_rn(v0.x, v0.y);
        __half2 h1 = __floats2half2_rn(v0.z, v0.w);
        __half2 h2 = __floats2half2_rn(v1.x, v1.y);
        __half2 h3 = __floats2half2_rn(v1.z, v1.w);
        uint4 u;
        u.x = *reinterpret_cast<uint32_t*>(&h0);
        u.y = *reinterpret_cast<uint32_t*>(&h1);
        u.z = *reinterpret_cast<uint32_t*>(&h2);
        u.w = *reinterpret_cast<uint32_t*>(&h3);
        *(uint4*)(sm + row * 1024 + (((c ^ (row & 7))) << 4)) = u;
    }

    // ---- strength-reduced LDSM constants ----
    const uint32_t a_row_addr = sb + (mg * 32 + (lane & 15)) * 1024;
    const int a_hi = lane >> 4;
    const int asw = lane & 7;
    uint32_t aoffC[4];
#pragma unroll
    for (int ks = 0; ks < 4; ks++)
        aoffC[ks] = (uint32_t)(((ks * 2 + a_hi) ^ asw) << 4);

    const int brow = (lane & 7) + ((lane & 16) >> 1);
    const int bkbit = (lane >> 3) & 1;
    const int bsw = lane & 7;
    uint32_t boffC[4];
#pragma unroll
    for (int ks = 0; ks < 4; ks++)
        boffC[ks] = (uint32_t)(((ks * 2 + bkbit) ^ bsw) << 4);
    const uint32_t bbase0 = sb_B + (uint32_t)ng * 32 * 128 + (uint32_t)(brow << 7);
    const uint32_t bbase1 = bbase0 + B_SZ;
    const uint32_t browoff1 = 16u << 7;

    float p[4] = {0.f, 0.f, 0.f, 0.f};
    const float bo0 = bo[0];

    for (int nt = 0; nt < 8; nt++) {
        float acc[2][4][4];
#pragma unroll
        for (int mt = 0; mt < 2; mt++)
#pragma unroll
            for (int nb = 0; nb < 4; nb++)
#pragma unroll
                for (int j = 0; j < 4; j++) acc[mt][nb][j] = 0.f;

        for (int kk = 0; kk < 8; kk++) {
            const int it = nt * 8 + kk;
            CP_WAIT0();
            __syncthreads();
            if (it + 1 < 64) fill_B(((it + 1) & 1) ? B_SZ : 0u, it + 1);

            const uint32_t bb = (it & 1) ? bbase1 : bbase0;
            const uint32_t arow = a_row_addr + ((uint32_t)kk << 7);
#pragma unroll
            for (int ks = 0; ks < 4; ks++) {
                uint32_t a[2][4];
                ldsm4(a[0][0], a[0][1], a[0][2], a[0][3], arow + aoffC[ks]);
                ldsm4(a[1][0], a[1][1], a[1][2], a[1][3], arow + 16384 + aoffC[ks]);
                uint32_t bf[2][4];
                ldsm4(bf[0][0], bf[0][1], bf[0][2], bf[0][3], bb + boffC[ks]);
                ldsm4(bf[1][0], bf[1][1], bf[1][2], bf[1][3], bb + browoff1 + boffC[ks]);
#pragma unroll
                for (int mt = 0; mt < 2; mt++)
#pragma unroll
                    for (int pq = 0; pq < 2; pq++) {
                        mma16816(acc[mt][2 * pq],     a[mt][0], a[mt][1], a[mt][2], a[mt][3],
                                 bf[pq][0], bf[pq][1]);
                        mma16816(acc[mt][2 * pq + 1], a[mt][0], a[mt][1], a[mt][2], a[mt][3],
                                 bf[pq][2], bf[pq][3]);
                    }
            }
        }

        // ---- fused epilogue for n-tile nt ----
#pragma unroll
        for (int mt = 0; mt < 2; mt++)
#pragma unroll
            for (int nb = 0; nb < 4; nb++) {
                const int ngl = nt * 128 + ng * 32 + nb * 8 + ((lane & 3) << 1);
                const float rq0 = rqs_s[ngl],     w0 = wos_s[ngl];
                const float rq1 = rqs_s[ngl + 1], w1 = wos_s[ngl + 1];
                p[2 * mt]     += w0 * tanh_mufu(acc[mt][nb][0] + rq0);
                p[2 * mt]     += w1 * tanh_mufu(acc[mt][nb][1] + rq1);
                p[2 * mt + 1] += w0 * tanh_mufu(acc[mt][nb][2] + rq0);
                p[2 * mt + 1] += w1 * tanh_mufu(acc[mt][nb][3] + rq1);
            }
    }

#pragma unroll
    for (int j = 0; j < 4; j++) {
        p[j] += __shfl_xor_sync(0xffffffffu, p[j], 1);
        p[j] += __shfl_xor_sync(0xffffffffu, p[j], 2);
    }
    if (ng > 0 && (lane & 3) == 0) {
        float* dst = red_s + (ng - 1) * 64 + mg * 32 + (lane >> 2);
        dst[0]  = p[0];
        dst[8]  = p[1];
        dst[16] = p[2];
        dst[24] = p[3];
    }
    __syncthreads();
    if (ng == 0 && (lane & 3) == 0) {
        const int r = mg * 32 + (lane >> 2);
#pragma unroll
        for (int j = 0; j < 4; j++) {
            const int row = r + 8 * j;
            if (m0 + row < cnt)
                g_logit[b * LL + m0 + row] = p[j] + red_s[row] + red_s[64 + row]
                                           + red_s[128 + row] + bo0;
        }
    }
}

// ---------------- kernel 3: masked exp + normalize (compacted) -------------
// Also zeroes the per-batch wsum arrival counter for the fused reduction.
__global__ void softmax_kernel(const float* __restrict__ mask,
                               float* __restrict__ w_out, int write_w) {
    __shared__ float sred[256];
    const int b = blockIdx.x, t = threadIdx.x;
    const int cnt = g_cnt[b];
    if (t == 0) g_wcnt[b] = 0;
    if (write_w) {
        for (int i = t; i < LL; i += 256) w_out[b * LL + i] = 0.f;
    }
    float e[8];
    int ids[8];
    float s = 0.f;
#pragma unroll
    for (int i = 0; i < 8; i++) {
        const int j = t + i * 256;
        float ev = 0.f;
        int id = -1;
        if (j < cnt) {
            id = g_idx[b * LL + j];
            ev = mask[b * LL + id] * expf(g_logit[b * LL + j]);
        }
        e[i] = ev;
        ids[i] = id;
        s += ev;
    }
    sred[t] = s;
    __syncthreads();
#pragma unroll
    for (int off = 128; off > 0; off >>= 1) {
        if (t < off) sred[t] += sred[t + off];
        __syncthreads();
    }
    const float inv = 1.f / (sred[0] + 1e-5f);
#pragma unroll
    for (int i = 0; i < 8; i++) {
        if (ids[i] >= 0) {
            const float wv = e[i] * inv;
            g_wcmp[b * LL + t + i * 256] = wv;
            if (write_w) w_out[b * LL + ids[i]] = wv;
        }
    }
}

// ---------------- kernel 4: weighted sum + fused last-block reduction ------
// 256 threads: 128 per row-half (float4 covers 512 cols). The 32nd-arriving
// CTA of each batch sums the 32 partials (fixed order -> deterministic) and
// writes out_vec directly — no separate reduce kernel.
__global__ void wsum_kernel(const float* __restrict__ ctx,
                            float* __restrict__ out_vec) {
    const int b = blockIdx.x, seg = blockIdx.y, t = threadIdx.x;
    const int cnt = g_cnt[b];
    const int tc = t & 127, half = t >> 7;
    float4* dstq = (float4*)(g_part + (size_t)(b * 32 + seg) * CC) + tc;

    if (seg * 64 >= cnt) {
        if (half == 0) *dstq = make_float4(0.f, 0.f, 0.f, 0.f);
    } else {
        __shared__ float ws[64];
        __shared__ int wi[64];
        __shared__ float4 xch[128];
        if (t < 64) {
            const int j = seg * 64 + t;
            if (j < cnt) { ws[t] = g_wcmp[b * LL + j]; wi[t] = g_idx[b * LL + j]; }
            else         { ws[t] = 0.f;                wi[t] = 0; }
        }
        __syncthreads();
        const float4* cb = (const float4*)(ctx + (size_t)b * LL * CC) + tc;
        float4 acc = make_float4(0.f, 0.f, 0.f, 0.f);
        float4 buf[8];
        float wv[8];
#pragma unroll
        for (int i = 0; i < 8; i++) {
            const int r = half + 2 * i;
            buf[i] = cb[(size_t)wi[r] * 128];
            wv[i] = ws[r];
        }
#pragma unroll
        for (int li = 0; li < 32; li++) {
            const float4 v = buf[li & 7];
            const float w = wv[li & 7];
            if (li + 8 < 32) {
                const int r = half + 2 * (li + 8);
                buf[li & 7] = cb[(size_t)wi[r] * 128];
                wv[li & 7] = ws[r];
            }
            acc.x = fmaf(w, v.x, acc.x);
            acc.y = fmaf(w, v.y, acc.y);
            acc.z = fmaf(w, v.z, acc.z);
            acc.w = fmaf(w, v.w, acc.w);
        }
        if (half == 1) xch[tc] = acc;
        __syncthreads();
        if (half == 0) {
            const float4 o = xch[tc];
            acc.x += o.x;
            acc.y += o.y;
            acc.z += o.z;
            acc.w += o.w;
            *dstq = acc;
        }
    }

    // ---- arrival + last-block final reduction ----
    __shared__ int is_last;
    __threadfence();                        // release partials
    __syncthreads();                        // all partial writes issued
    if (t == 0) {
        const int prev = atomicAdd(&g_wcnt[b], 1);
        is_last = (prev == 31) ? 1 : 0;
    }
    __syncthreads();
    if (is_last && out_vec != nullptr) {
        __threadfence();                    // acquire all partials
        const int c = t * 2;                // 256 threads x 2 cols = 512
        float s0 = 0.f, s1 = 0.f;
        const float* pp = g_part + (size_t)b * 32 * CC + c;
#pragma unroll
        for (int ls = 0; ls < 32; ls++) {
            const float2 v = *(const float2*)(pp + (size_t)ls * CC);
            s0 += v.x;
            s1 += v.y;
        }
        *(float2*)(out_vec + b * CC + c) = make_float2(s0, s1);
    }
}

// ---------------- launch ----------------
extern "C" void kernel_launch(void* const* d_in, const int* in_sizes, int n_in,
                              void* d_out, int out_size) {
    const float* query   = (const float*)d_in[0];
    const float* context = (const float*)d_in[1];
    const float* mask    = (const float*)d_in[2];
    const float* Wq      = (const float*)d_in[3];
    const float* Wc      = (const float*)d_in[4];
    const float* bc      = (const float*)d_in[5];
    const float* Wo      = (const float*)d_in[6];
    const float* bo      = (const float*)d_in[7];

    float* out = (float*)d_out;
    float* out_vec = nullptr;
    float* out_w = nullptr;
    if (out_size >= BB * CC + BB * LL) {
        out_vec = out;
        out_w = out + BB * CC;
    } else if (out_size == BB * LL) {
        out_w = out;
    } else {
        out_vec = out;
    }

    cudaFuncSetAttribute(logits_mma_kernel,
                         cudaFuncAttributeMaxDynamicSharedMemorySize, SM_REQ);

    prep_kernel<<<672, 256>>>(Wc, query, Wq, mask);
    logits_mma_kernel<<<(BB * LL) / 64, 256, SM_REQ>>>(context, bc, Wo, bo);
    softmax_kernel<<<BB, 256>>>(mask, out_w, out_w != nullptr ? 1 : 0);
    wsum_kernel<<<dim3(BB, 32), 256>>>(context, out_vec);
}